// round 16
// baseline (speedup 1.0000x reference)
#include <cuda_runtime.h>
#include <cuda_bf16.h>
#include <math.h>
#include <stdint.h>

#define BS_TOT 4096
#define S_LEN  2048
#define D_EMB  1536
#define D_AUG  512

// ---------------- device scratch ----------------
__device__ float g_qh[BS_TOT * D_AUG];
__device__ float g_kh[BS_TOT * D_AUG];
__device__ float g_vh[BS_TOT * D_AUG];
__device__ float g_rope[2 * S_LEN * 64];   // cos | sin

// 2-plane stored operands [hi|lo]; the GEMM loader remaps the logical
// 3-segment layouts (A: hi,hi,lo / B: hi,lo,hi) onto these planes.
__device__ __align__(128) __nv_bfloat16 g_q_s   [BS_TOT * 2 * D_EMB];
__device__ __align__(128) __nv_bfloat16 g_k_s   [BS_TOT * 2 * D_EMB];
__device__ __align__(128) __nv_bfloat16 g_v_s   [BS_TOT * 2 * D_AUG];
__device__ __align__(128) __nv_bfloat16 g_attn_s[BS_TOT * 2 * D_AUG];
__device__ __align__(128) __nv_bfloat16 g_Wq_s  [D_AUG * 2 * D_EMB];
__device__ __align__(128) __nv_bfloat16 g_Wk_s  [D_AUG * 2 * D_EMB];
__device__ __align__(128) __nv_bfloat16 g_Wv_s  [D_AUG * 2 * D_AUG];
__device__ __align__(128) __nv_bfloat16 g_Wo_s  [D_EMB * 2 * D_AUG];

__device__ __align__(128) __nv_bfloat16 g_qhi[8 * S_LEN * 128];
__device__ __align__(128) __nv_bfloat16 g_qlo[8 * S_LEN * 128];
__device__ __align__(128) __nv_bfloat16 g_khi[8 * S_LEN * 128];
__device__ __align__(128) __nv_bfloat16 g_klo[8 * S_LEN * 128];
__device__ __align__(128) __nv_bfloat16 g_vthi[8 * 128 * S_LEN];
__device__ __align__(128) __nv_bfloat16 g_vtlo[8 * 128 * S_LEN];

extern __shared__ __align__(128) char dynsmem[];

// ---------------------------------------------------------------------------
__device__ __forceinline__ uint32_t smem_u32(const void* p) {
    uint32_t a;
    asm("{ .reg .u64 t; cvta.to.shared.u64 t, %1; cvt.u32.u64 %0, t; }" : "=r"(a) : "l"(p));
    return a;
}
__device__ __forceinline__ void cp16(uint32_t saddr, const void* gaddr) {
    asm volatile("cp.async.cg.shared.global [%0], [%1], 16;" :: "r"(saddr), "l"(gaddr) : "memory");
}
__device__ __forceinline__ void cp_commit() {
    asm volatile("cp.async.commit_group;" ::: "memory");
}
template <int N>
__device__ __forceinline__ void cp_wait() {
    asm volatile("cp.async.wait_group %0;" :: "n"(N) : "memory");
}
__device__ __forceinline__ void ldmx4(uint32_t* r, uint32_t addr) {
    asm volatile("ldmatrix.sync.aligned.m8n8.x4.shared.b16 {%0,%1,%2,%3}, [%4];"
                 : "=r"(r[0]), "=r"(r[1]), "=r"(r[2]), "=r"(r[3]) : "r"(addr));
}
__device__ __forceinline__ void mma_bf16(float* c, const uint32_t* a, uint32_t b0, uint32_t b1) {
    asm volatile(
        "mma.sync.aligned.m16n8k16.row.col.f32.bf16.bf16.f32 "
        "{%0,%1,%2,%3}, {%4,%5,%6,%7}, {%8,%9}, {%0,%1,%2,%3};"
        : "+f"(c[0]), "+f"(c[1]), "+f"(c[2]), "+f"(c[3])
        : "r"(a[0]), "r"(a[1]), "r"(a[2]), "r"(a[3]), "r"(b0), "r"(b1));
}
__device__ __forceinline__ float ex2(float x) {
    float y; asm("ex2.approx.f32 %0, %1;" : "=f"(y) : "f"(x)); return y;
}

// ---------------------------------------------------------------------------
// split: dst rows [hi | lo], length 2K
// ---------------------------------------------------------------------------
__device__ __forceinline__ void split2_row(const float* srow, __nv_bfloat16* drow,
                                           int K, int c4)
{
    float4 x = *(const float4*)(srow + c4);
    float xs[4] = {x.x, x.y, x.z, x.w};
    __nv_bfloat162 h0, h1, l0, l1;
    __nv_bfloat16 h[4], l[4];
#pragma unroll
    for (int j = 0; j < 4; j++) {
        h[j] = __float2bfloat16(xs[j]);
        l[j] = __float2bfloat16(xs[j] - __bfloat162float(h[j]));
    }
    h0.x = h[0]; h0.y = h[1]; h1.x = h[2]; h1.y = h[3];
    l0.x = l[0]; l0.y = l[1]; l1.x = l[2]; l1.y = l[3];
    __nv_bfloat16* d = drow + c4;
    *(__nv_bfloat162*)(d)     = h0;  *(__nv_bfloat162*)(d + 2)     = h1;
    *(__nv_bfloat162*)(d + K) = l0;  *(__nv_bfloat162*)(d + K + 2) = l1;
}

__global__ void split_qk_kernel(const float* __restrict__ q, const float* __restrict__ k,
                                __nv_bfloat16* __restrict__ qs, __nv_bfloat16* __restrict__ ks)
{
    int i = blockIdx.x * blockDim.x + threadIdx.x;       // 8192*384
    int rt = i / 384, c4 = (i - rt * 384) << 2;
    const float* src = (rt < 4096) ? q : k;
    __nv_bfloat16* dst = (rt < 4096) ? qs : ks;
    int r = rt & 4095;
    split2_row(src + (size_t)r * D_EMB, dst + (size_t)r * 2 * D_EMB, D_EMB, c4);
}

__global__ void split_wqk_kernel(const float* __restrict__ Wq, const float* __restrict__ Wk,
                                 __nv_bfloat16* __restrict__ wqs, __nv_bfloat16* __restrict__ wks)
{
    int i = blockIdx.x * blockDim.x + threadIdx.x;       // 1024*384
    int rt = i / 384, c4 = (i - rt * 384) << 2;
    const float* src = (rt < 512) ? Wq : Wk;
    __nv_bfloat16* dst = (rt < 512) ? wqs : wks;
    int r = rt & 511;
    split2_row(src + (size_t)r * D_EMB, dst + (size_t)r * 2 * D_EMB, D_EMB, c4);
}

// v (4096 rows, stride D_EMB, offset D_AUG), Wv (512, stride D_AUG),
// Wo (1536 rows, stride D_EMB — W_o is 1536x1536, cols [0,512)).
__global__ void split_vwo_kernel(const float* __restrict__ v, const float* __restrict__ Wv,
                                 const float* __restrict__ Wo,
                                 __nv_bfloat16* __restrict__ vs, __nv_bfloat16* __restrict__ wvs,
                                 __nv_bfloat16* __restrict__ wos)
{
    int i = blockIdx.x * blockDim.x + threadIdx.x;       // 6144*128
    int rt = i >> 7, c4 = (i & 127) << 2;
    if (rt < 4096) {
        split2_row(v + (size_t)rt * D_EMB + D_AUG, vs + (size_t)rt * 2 * D_AUG, D_AUG, c4);
    } else if (rt < 4608) {
        int r = rt - 4096;
        split2_row(Wv + (size_t)r * D_AUG, wvs + (size_t)r * 2 * D_AUG, D_AUG, c4);
    } else {
        int r = rt - 4608;
        split2_row(Wo + (size_t)r * D_EMB, wos + (size_t)r * 2 * D_AUG, D_AUG, c4);
    }
}

// ---------------------------------------------------------------------------
// HMMA GEMM core: logical C = A3 @ B3^T with A3 = [hi|hi|lo], B3 = [hi|lo|hi]
// over 3K, sourced from physical [hi|lo] planes (row stride 2K) via segment
// remap. MMA sequence identical to the explicit 3K layout -> bit-identical.
// ---------------------------------------------------------------------------
#define BM 128
#define BN 128
#define BK 32
#define LDSM 40
#define STAGES 3
#define TSTG (BM * LDSM)
#define GEMM_SMEM (2 * STAGES * TSTG * 2)

// logical chunk it (0..3*Kc-1) -> physical element offsets for A and B
__device__ __forceinline__ void seg_remap(int it, int Kc, int K, int& a_k0, int& b_k0)
{
    int seg = (it >= 2 * Kc) ? 2 : (it >= Kc ? 1 : 0);
    int rem = it - seg * Kc;
    a_k0 = ((seg == 2) ? K : 0) + rem * BK;   // A: hi, hi, lo
    b_k0 = ((seg == 1) ? K : 0) + rem * BK;   // B: hi, lo, hi
}

__device__ __forceinline__ void gemm_body(const __nv_bfloat16* __restrict__ A,
                                          const __nv_bfloat16* __restrict__ B,
                                          float* __restrict__ C, int Kb, int ldc,
                                          int m0, int n0)
{
    __nv_bfloat16* As = (__nv_bfloat16*)dynsmem;
    __nv_bfloat16* Bs = As + STAGES * TSTG;

    const int tid  = threadIdx.x;
    const int wid  = tid >> 5, lane = tid & 31;
    const int wm   = (wid >> 2) * 64;
    const int wn   = (wid & 3) * 32;
    const int lda  = 2 * Kb;
    const int Kc   = Kb / BK;
    const int KT   = 3 * Kc;

    const int lrow0 = tid >> 2,         lq0 = tid & 3;
    const int lrow1 = (tid + 256) >> 2, lq1 = (tid + 256) & 3;

    const __nv_bfloat16* Ag0 = A + (size_t)(m0 + lrow0) * lda + lq0 * 8;
    const __nv_bfloat16* Ag1 = A + (size_t)(m0 + lrow1) * lda + lq1 * 8;
    const __nv_bfloat16* Bg0 = B + (size_t)(n0 + lrow0) * lda + lq0 * 8;
    const __nv_bfloat16* Bg1 = B + (size_t)(n0 + lrow1) * lda + lq1 * 8;
    const uint32_t sA0 = smem_u32(As) + (lrow0 * LDSM + lq0 * 8) * 2;
    const uint32_t sA1 = smem_u32(As) + (lrow1 * LDSM + lq1 * 8) * 2;
    const uint32_t sB0 = smem_u32(Bs) + (lrow0 * LDSM + lq0 * 8) * 2;
    const uint32_t sB1 = smem_u32(Bs) + (lrow1 * LDSM + lq1 * 8) * 2;

    float acc[4][4][4];
#pragma unroll
    for (int i = 0; i < 4; i++)
#pragma unroll
        for (int j = 0; j < 4; j++)
#pragma unroll
            for (int t = 0; t < 4; t++) acc[i][j][t] = 0.f;

    const uint32_t als = smem_u32(As) + ((wm + (lane & 15)) * LDSM + (lane >> 4) * 8) * 2;
    const uint32_t bls = smem_u32(Bs) + ((wn + (lane & 15)) * LDSM + (lane >> 4) * 8) * 2;

#pragma unroll
    for (int s = 0; s < STAGES - 1; s++) {
        int ak0, bk0;
        seg_remap(s, Kc, Kb, ak0, bk0);
        cp16(sA0 + s * TSTG * 2, Ag0 + ak0);
        cp16(sA1 + s * TSTG * 2, Ag1 + ak0);
        cp16(sB0 + s * TSTG * 2, Bg0 + bk0);
        cp16(sB1 + s * TSTG * 2, Bg1 + bk0);
        cp_commit();
    }

    for (int it = 0; it < KT; it++) {
        cp_wait<STAGES - 2>();
        __syncthreads();
        const int sc = it % STAGES;
        const uint32_t abase = als + sc * TSTG * 2;
        const uint32_t bbase = bls + sc * TSTG * 2;
#pragma unroll
        for (int ks = 0; ks < 2; ks++) {
            uint32_t af[4][4], bf[2][4];
#pragma unroll
            for (int mt = 0; mt < 4; mt++)
                ldmx4(af[mt], abase + (mt * 16 * LDSM + ks * 16) * 2);
#pragma unroll
            for (int nt2 = 0; nt2 < 2; nt2++)
                ldmx4(bf[nt2], bbase + (nt2 * 16 * LDSM + ks * 16) * 2);
#pragma unroll
            for (int mt = 0; mt < 4; mt++)
#pragma unroll
                for (int nt = 0; nt < 4; nt++)
                    mma_bf16(acc[mt][nt], af[mt],
                             bf[nt >> 1][nt & 1], bf[nt >> 1][(nt & 1) + 2]);
        }
        const int nxt = it + STAGES - 1;
        if (nxt < KT) {
            const int sn = nxt % STAGES;
            int ak0, bk0;
            seg_remap(nxt, Kc, Kb, ak0, bk0);
            cp16(sA0 + sn * TSTG * 2, Ag0 + ak0);
            cp16(sA1 + sn * TSTG * 2, Ag1 + ak0);
            cp16(sB0 + sn * TSTG * 2, Bg0 + bk0);
            cp16(sB1 + sn * TSTG * 2, Bg1 + bk0);
        }
        cp_commit();
    }

    const int rbase = m0 + wm + (lane >> 2);
    const int cbase = n0 + wn + (lane & 3) * 2;
#pragma unroll
    for (int mt = 0; mt < 4; mt++) {
#pragma unroll
        for (int nt = 0; nt < 4; nt++) {
            float* p0 = C + (size_t)(rbase + mt * 16) * ldc + cbase + nt * 8;
            float* p1 = p0 + 8 * ldc;
            *(float2*)p0 = make_float2(acc[mt][nt][0], acc[mt][nt][1]);
            *(float2*)p1 = make_float2(acc[mt][nt][2], acc[mt][nt][3]);
        }
    }
}

// o-projection launch (Kb = D_AUG)
__global__ void __launch_bounds__(256, 2)
gemm_hmma(const __nv_bfloat16* __restrict__ A, const __nv_bfloat16* __restrict__ B,
          float* __restrict__ C, int Kb, int ldc)
{
    gemm_body(A, B, C, Kb, ldc, blockIdx.y * BM, blockIdx.x * BN);
}

// Batched q+k+v projections (Kb: qk = D_EMB, v = D_AUG)
__global__ void __launch_bounds__(256, 2)
gemm_qkv3(const __nv_bfloat16* __restrict__ A0, const __nv_bfloat16* __restrict__ B0, float* __restrict__ C0,
          const __nv_bfloat16* __restrict__ A1, const __nv_bfloat16* __restrict__ B1, float* __restrict__ C1,
          const __nv_bfloat16* __restrict__ A2, const __nv_bfloat16* __restrict__ B2, float* __restrict__ C2,
          int Kbqk, int Kbv, int ldc)
{
    const int z = blockIdx.z;
    const __nv_bfloat16* A = (z == 0) ? A0 : (z == 1) ? A1 : A2;
    const __nv_bfloat16* B = (z == 0) ? B0 : (z == 1) ? B1 : B2;
    float* C = (z == 0) ? C0 : (z == 1) ? C1 : C2;
    const int Kb = (z == 2) ? Kbv : Kbqk;
    gemm_body(A, B, C, Kb, ldc, blockIdx.y * BM, blockIdx.x * BN);
}

// ---------------------------------------------------------------------------
// RoPE table
// ---------------------------------------------------------------------------
__global__ void rope_table_kernel(float* __restrict__ tab)
{
    int idx = blockIdx.x * blockDim.x + threadIdx.x;   // 2048*64
    if (idx >= S_LEN * 64) return;
    int pair = idx & 63, s = idx >> 6;
    float freq = (float)exp(-(double)(2 * pair) * (1.0 / 128.0) * 9.210340371976184);
    float ang  = (float)s * freq;
    tab[idx]              = cosf(ang);
    tab[S_LEN * 64 + idx] = sinf(ang);
}

// ---------------------------------------------------------------------------
// RoPE + split-bf16 plane emission
// ---------------------------------------------------------------------------
__global__ void rope_split_kernel(const float* __restrict__ qh, const float* __restrict__ kh,
                                  const float* __restrict__ tab,
                                  __nv_bfloat16* __restrict__ qhi, __nv_bfloat16* __restrict__ qlo,
                                  __nv_bfloat16* __restrict__ khi, __nv_bfloat16* __restrict__ klo)
{
    int idx  = blockIdx.x * blockDim.x + threadIdx.x;  // 8*2048*64
    int pair = idx & 63;
    int s    = (idx >> 6) & (S_LEN - 1);
    int bh   = idx >> 17;
    int b = bh >> 2, h = bh & 3;

    float c  = tab[s * 64 + pair];
    float sn = tab[S_LEN * 64 + s * 64 + pair];

    size_t src = (size_t)(b * S_LEN + s) * D_AUG + h * 128 + 2 * pair;
    size_t dst = (size_t)bh * S_LEN * 128 + (size_t)s * 128 + 2 * pair;
    const float qscale = 0.08838834764831845f;

    float q1 = qh[src], q2 = qh[src + 1];
    float qa = (q1 * c - q2 * sn) * qscale;
    float qb = (q1 * sn + q2 * c) * qscale;
    __nv_bfloat16 ha = __float2bfloat16(qa), hb = __float2bfloat16(qb);
    __nv_bfloat162 hv; hv.x = ha; hv.y = hb;
    __nv_bfloat162 lv;
    lv.x = __float2bfloat16(qa - __bfloat162float(ha));
    lv.y = __float2bfloat16(qb - __bfloat162float(hb));
    *(__nv_bfloat162*)(qhi + dst) = hv;
    *(__nv_bfloat162*)(qlo + dst) = lv;

    float k1 = kh[src], k2 = kh[src + 1];
    float ka = k1 * c - k2 * sn;
    float kb = k1 * sn + k2 * c;
    ha = __float2bfloat16(ka); hb = __float2bfloat16(kb);
    hv.x = ha; hv.y = hb;
    lv.x = __float2bfloat16(ka - __bfloat162float(ha));
    lv.y = __float2bfloat16(kb - __bfloat162float(hb));
    *(__nv_bfloat162*)(khi + dst) = hv;
    *(__nv_bfloat162*)(klo + dst) = lv;
}

// ---------------------------------------------------------------------------
// V transpose + split
// ---------------------------------------------------------------------------
__global__ void vt_split_kernel(const float* __restrict__ vh,
                                __nv_bfloat16* __restrict__ vthi, __nv_bfloat16* __restrict__ vtlo)
{
    __shared__ float tile[32][33];
    int bh = blockIdx.z, b = bh >> 2, h = bh & 3;
    int tx = threadIdx.x, ty = threadIdx.y;
    int s_in = blockIdx.x * 32 + ty;
    int d_in = blockIdx.y * 32 + tx;
    tile[ty][tx] = vh[(size_t)(b * S_LEN + s_in) * D_AUG + h * 128 + d_in];
    __syncthreads();
    int d_out = blockIdx.y * 32 + ty;
    int s_out = blockIdx.x * 32 + tx;
    float v = tile[tx][ty];
    __nv_bfloat16 hi = __float2bfloat16(v);
    size_t dst = (size_t)bh * 128 * S_LEN + (size_t)d_out * S_LEN + s_out;
    vthi[dst] = hi;
    vtlo[dst] = __float2bfloat16(v - __bfloat162float(hi));
}

// ---------------------------------------------------------------------------
// HMMA flash attention with double-buffered K/V (R13-exact mainloop;
// epilogue writes [hi|lo] rows for the remapped o-projection).
// ---------------------------------------------------------------------------
#define FB_QHI  0
#define FB_QLO  17408
#define FB_KV0  34816
#define FB_KV1  106496
#define KV_KHI  0
#define KV_KLO  17408
#define KV_VHI  34816
#define KV_VLO  53248
#define FB_PHI  178176
#define FB_PLO  187392
#define FB_RED  196608
#define FB_SMEM 197632
#define L2E 1.4426950408889634f

__global__ void __launch_bounds__(256, 1)
flash_hmma(const __nv_bfloat16* __restrict__ qhi, const __nv_bfloat16* __restrict__ qlo,
           const __nv_bfloat16* __restrict__ khi, const __nv_bfloat16* __restrict__ klo,
           const __nv_bfloat16* __restrict__ vthi, const __nv_bfloat16* __restrict__ vtlo,
           __nv_bfloat16* __restrict__ attn_s)
{
    char* fsm = dynsmem;
    const uint32_t sb = smem_u32(fsm);
    float* red = (float*)(fsm + FB_RED);

    const int tid  = threadIdx.x;
    const int lane = tid & 31;
    const int wid  = tid >> 5;
    const int mw   = wid >> 1;
    const int nw   = wid & 1;
    const int bh   = blockIdx.y;
    const int b    = bh >> 2, hh = bh & 3;

    const size_t qkplane = (size_t)bh * S_LEN * 128;
    const size_t vplane  = (size_t)bh * 128 * S_LEN;

    const uint32_t aoffQ = (mw * 16 + (lane & 15)) * 272 + (lane >> 4) * 16;
    const uint32_t boffK = (nw * 32 + (lane & 15)) * 272 + (lane >> 4) * 16;
    const uint32_t aoffP = (mw * 16 + (lane & 15)) * 144 + (lane >> 4) * 16;
    const uint32_t boffV = (nw * 64 + (lane & 15)) * 144 + (lane >> 4) * 16;

    const int r0 = lane >> 2;
    const int c2 = (lane & 3) * 2;
    const int rloc0 = mw * 16 + r0;
    const int rloc1 = rloc0 + 8;

    const int kr[4]  = {tid >> 4, (tid + 256) >> 4, (tid + 512) >> 4, (tid + 768) >> 4};
    const int kq[4]  = {tid & 15, (tid + 256) & 15, (tid + 512) & 15, (tid + 768) & 15};
    const int vr[4]  = {tid >> 3, (tid + 256) >> 3, (tid + 512) >> 3, (tid + 768) >> 3};
    const int vq[4]  = {tid & 7,  (tid + 256) & 7,  (tid + 512) & 7,  (tid + 768) & 7};

    for (int qq = 0; qq < 2; qq++) {
        const int qb = qq ? 31 - (int)blockIdx.x : (int)blockIdx.x;

        __syncthreads();
        {
            const __nv_bfloat16* srcs[2] = {qhi + qkplane + (size_t)qb * 64 * 128,
                                            qlo + qkplane + (size_t)qb * 64 * 128};
#pragma unroll
            for (int p = 0; p < 2; p++)
#pragma unroll
                for (int i = 0; i < 4; i++)
                    cp16(sb + FB_QHI + p * 17408 + kr[i] * 272 + kq[i] * 16,
                         srcs[p] + (size_t)kr[i] * 128 + kq[i] * 8);
            cp_commit();
        }
        {
            const __nv_bfloat16* ks[2] = {khi + qkplane, klo + qkplane};
            const __nv_bfloat16* vs[2] = {vthi + vplane, vtlo + vplane};
#pragma unroll
            for (int p = 0; p < 2; p++)
#pragma unroll
                for (int i = 0; i < 4; i++)
                    cp16(sb + FB_KV0 + KV_KHI + p * 17408 + kr[i] * 272 + kq[i] * 16,
                         ks[p] + (size_t)kr[i] * 128 + kq[i] * 8);
#pragma unroll
            for (int p = 0; p < 2; p++)
#pragma unroll
                for (int i = 0; i < 4; i++)
                    cp16(sb + FB_KV0 + KV_VHI + p * 18432 + vr[i] * 144 + vq[i] * 16,
                         vs[p] + (size_t)vr[i] * S_LEN + vq[i] * 8);
            cp_commit();
        }

        float m0 = -1e30f, m1 = -1e30f, l0 = 0.f, l1 = 0.f;
        float o[8][4];
#pragma unroll
        for (int f = 0; f < 8; f++)
#pragma unroll
            for (int e = 0; e < 4; e++) o[f][e] = 0.f;

        for (int jb = 0; jb <= qb; jb++) {
            __syncthreads();
            if (jb < qb) {
                const int nj = jb + 1;
                const uint32_t nb = sb + ((nj & 1) ? FB_KV1 : FB_KV0);
                const __nv_bfloat16* ks[2] = {khi + qkplane + (size_t)nj * 64 * 128,
                                              klo + qkplane + (size_t)nj * 64 * 128};
                const __nv_bfloat16* vs[2] = {vthi + vplane + nj * 64,
                                              vtlo + vplane + nj * 64};
#pragma unroll
                for (int p = 0; p < 2; p++)
#pragma unroll
                    for (int i = 0; i < 4; i++)
                        cp16(nb + KV_KHI + p * 17408 + kr[i] * 272 + kq[i] * 16,
                             ks[p] + (size_t)kr[i] * 128 + kq[i] * 8);
#pragma unroll
                for (int p = 0; p < 2; p++)
#pragma unroll
                    for (int i = 0; i < 4; i++)
                        cp16(nb + KV_VHI + p * 18432 + vr[i] * 144 + vq[i] * 16,
                             vs[p] + (size_t)vr[i] * S_LEN + vq[i] * 8);
            }
            cp_commit();
            cp_wait<1>();
            __syncthreads();

            const uint32_t kvb = sb + ((jb & 1) ? FB_KV1 : FB_KV0);

            float sacc[4][4];
#pragma unroll
            for (int f = 0; f < 4; f++)
#pragma unroll
                for (int e = 0; e < 4; e++) sacc[f][e] = 0.f;

            const uint32_t aB[3] = {sb + FB_QHI, sb + FB_QHI, sb + FB_QLO};
            const uint32_t bB[3] = {kvb + KV_KHI, kvb + KV_KLO, kvb + KV_KHI};
#pragma unroll
            for (int ps = 0; ps < 3; ps++) {
                const uint32_t ab = aB[ps] + aoffQ;
                const uint32_t bb0 = bB[ps] + boffK;
                const uint32_t bb1 = bb0 + 16 * 272;
#pragma unroll
                for (int ks = 0; ks < 8; ks++) {
                    uint32_t a[4], q0[4], q1[4];
                    ldmx4(a,  ab  + ks * 32);
                    ldmx4(q0, bb0 + ks * 32);
                    ldmx4(q1, bb1 + ks * 32);
                    mma_bf16(sacc[0], a, q0[0], q0[2]);
                    mma_bf16(sacc[1], a, q0[1], q0[3]);
                    mma_bf16(sacc[2], a, q1[0], q1[2]);
                    mma_bf16(sacc[3], a, q1[1], q1[3]);
                }
            }

            if (jb == qb) {
#pragma unroll
                for (int f = 0; f < 4; f++) {
                    int colb = nw * 32 + (f >> 1) * 16 + (f & 1) * 8 + c2;
#pragma unroll
                    for (int e = 0; e < 4; e++) {
                        int row = mw * 16 + r0 + ((e >> 1) << 3);
                        int col = colb + (e & 1);
                        if (col > row) sacc[f][e] = -1e30f;
                    }
                }
            }

            float pm0 = -1e30f, pm1 = -1e30f;
#pragma unroll
            for (int f = 0; f < 4; f++) {
                pm0 = fmaxf(pm0, fmaxf(sacc[f][0], sacc[f][1]));
                pm1 = fmaxf(pm1, fmaxf(sacc[f][2], sacc[f][3]));
            }
            pm0 = fmaxf(pm0, __shfl_xor_sync(0xffffffffu, pm0, 1));
            pm0 = fmaxf(pm0, __shfl_xor_sync(0xffffffffu, pm0, 2));
            pm1 = fmaxf(pm1, __shfl_xor_sync(0xffffffffu, pm1, 1));
            pm1 = fmaxf(pm1, __shfl_xor_sync(0xffffffffu, pm1, 2));
            if ((lane & 3) == 0) {
                red[nw * 64 + rloc0] = pm0;
                red[nw * 64 + rloc1] = pm1;
            }
            __syncthreads();
            float rm0 = fmaxf(red[rloc0], red[64 + rloc0]);
            float rm1 = fmaxf(red[rloc1], red[64 + rloc1]);
            float mn0 = fmaxf(m0, rm0), mn1 = fmaxf(m1, rm1);
            float scl0 = ex2((m0 - mn0) * L2E);
            float scl1 = ex2((m1 - mn1) * L2E);

            float ts0 = 0.f, ts1 = 0.f;
#pragma unroll
            for (int f = 0; f < 4; f++) {
                int col = nw * 32 + (f >> 1) * 16 + (f & 1) * 8 + c2;
                float p00 = ex2((sacc[f][0] - mn0) * L2E);
                float p01 = ex2((sacc[f][1] - mn0) * L2E);
                float p10 = ex2((sacc[f][2] - mn1) * L2E);
                float p11 = ex2((sacc[f][3] - mn1) * L2E);
                ts0 += p00 + p01;
                ts1 += p10 + p11;
                __nv_bfloat16 h00 = __float2bfloat16(p00), h01 = __float2bfloat16(p01);
                __nv_bfloat16 h10 = __float2bfloat16(p10), h11 = __float2bfloat16(p11);
                __nv_bfloat162 hv, lv;
                hv.x = h00; hv.y = h01;
                lv.x = __float2bfloat16(p00 - __bfloat162float(h00));
                lv.y = __float2bfloat16(p01 - __bfloat162float(h01));
                *(__nv_bfloat162*)(fsm + FB_PHI + rloc0 * 144 + col * 2) = hv;
                *(__nv_bfloat162*)(fsm + FB_PLO + rloc0 * 144 + col * 2) = lv;
                hv.x = h10; hv.y = h11;
                lv.x = __float2bfloat16(p10 - __bfloat162float(h10));
                lv.y = __float2bfloat16(p11 - __bfloat162float(h11));
                *(__nv_bfloat162*)(fsm + FB_PHI + rloc1 * 144 + col * 2) = hv;
                *(__nv_bfloat162*)(fsm + FB_PLO + rloc1 * 144 + col * 2) = lv;
            }
            ts0 += __shfl_xor_sync(0xffffffffu, ts0, 1);
            ts0 += __shfl_xor_sync(0xffffffffu, ts0, 2);
            ts1 += __shfl_xor_sync(0xffffffffu, ts1, 1);
            ts1 += __shfl_xor_sync(0xffffffffu, ts1, 2);
            if ((lane & 3) == 0) {
                red[128 + nw * 64 + rloc0] = ts0;
                red[128 + nw * 64 + rloc1] = ts1;
            }
            __syncthreads();
            l0 = l0 * scl0 + red[128 + rloc0] + red[128 + 64 + rloc0];
            l1 = l1 * scl1 + red[128 + rloc1] + red[128 + 64 + rloc1];
            m0 = mn0; m1 = mn1;
#pragma unroll
            for (int f = 0; f < 8; f++) {
                o[f][0] *= scl0; o[f][1] *= scl0;
                o[f][2] *= scl1; o[f][3] *= scl1;
            }

            const uint32_t aP[3] = {sb + FB_PHI, sb + FB_PHI, sb + FB_PLO};
            const uint32_t bV[3] = {kvb + KV_VHI, kvb + KV_VLO, kvb + KV_VHI};
#pragma unroll
            for (int ps = 0; ps < 3; ps++) {
                const uint32_t ab = aP[ps] + aoffP;
                const uint32_t bb = bV[ps] + boffV;
#pragma unroll
                for (int ks = 0; ks < 4; ks++) {
                    uint32_t a[4];
                    ldmx4(a, ab + ks * 32);
#pragma unroll
                    for (int g2 = 0; g2 < 4; g2++) {
                        uint32_t qv[4];
                        ldmx4(qv, bb + g2 * (16 * 144) + ks * 32);
                        mma_bf16(o[g2 * 2 + 0], a, qv[0], qv[2]);
                        mma_bf16(o[g2 * 2 + 1], a, qv[1], qv[3]);
                    }
                }
            }
        }

        // epilogue: write [hi | lo] rows of attn_s (2*D_AUG per row)
        float inv0 = 1.0f / l0, inv1 = 1.0f / l1;
        size_t rg0 = (size_t)(b * S_LEN + qb * 64 + rloc0) * (2 * D_AUG);
        size_t rg1 = (size_t)(b * S_LEN + qb * 64 + rloc1) * (2 * D_AUG);
#pragma unroll
        for (int f = 0; f < 8; f++) {
            int col = hh * 128 + nw * 64 + (f >> 1) * 16 + (f & 1) * 8 + c2;
            float v0 = o[f][0] * inv0, v1 = o[f][1] * inv0;
            __nv_bfloat16 h0 = __float2bfloat16(v0), h1 = __float2bfloat16(v1);
            __nv_bfloat162 hv, lv;
            hv.x = h0; hv.y = h1;
            lv.x = __float2bfloat16(v0 - __bfloat162float(h0));
            lv.y = __float2bfloat16(v1 - __bfloat162float(h1));
            *(__nv_bfloat162*)(attn_s + rg0 + col)         = hv;
            *(__nv_bfloat162*)(attn_s + rg0 + col + D_AUG) = lv;
            v0 = o[f][2] * inv1; v1 = o[f][3] * inv1;
            h0 = __float2bfloat16(v0); h1 = __float2bfloat16(v1);
            hv.x = h0; hv.y = h1;
            lv.x = __float2bfloat16(v0 - __bfloat162float(h0));
            lv.y = __float2bfloat16(v1 - __bfloat162float(h1));
            *(__nv_bfloat162*)(attn_s + rg1 + col)         = hv;
            *(__nv_bfloat162*)(attn_s + rg1 + col + D_AUG) = lv;
        }
    }
}

// ---------------------------------------------------------------------------
extern "C" void kernel_launch(void* const* d_in, const int* in_sizes, int n_in,
                              void* d_out, int out_size)
{
    const float* q  = (const float*)d_in[0];
    const float* k  = (const float*)d_in[1];
    const float* v  = (const float*)d_in[2];
    const float* Wq = (const float*)d_in[3];
    const float* Wk = (const float*)d_in[4];
    const float* Wv = (const float*)d_in[5];
    const float* Wo = (const float*)d_in[6];
    float* out = (float*)d_out;

    float *qh, *kh, *vh, *rtab;
    cudaGetSymbolAddress((void**)&qh,   g_qh);
    cudaGetSymbolAddress((void**)&kh,   g_kh);
    cudaGetSymbolAddress((void**)&vh,   g_vh);
    cudaGetSymbolAddress((void**)&rtab, g_rope);
    __nv_bfloat16 *qs, *ks, *vs, *ats, *wqs, *wks, *wvs, *wos;
    __nv_bfloat16 *pqhi, *pqlo, *pkhi, *pklo, *pvthi, *pvtlo;
    cudaGetSymbolAddress((void**)&qs,  g_q_s);
    cudaGetSymbolAddress((void**)&ks,  g_k_s);
    cudaGetSymbolAddress((void**)&vs,  g_v_s);
    cudaGetSymbolAddress((void**)&ats, g_attn_s);
    cudaGetSymbolAddress((void**)&wqs, g_Wq_s);
    cudaGetSymbolAddress((void**)&wks, g_Wk_s);
    cudaGetSymbolAddress((void**)&wvs, g_Wv_s);
    cudaGetSymbolAddress((void**)&wos, g_Wo_s);
    cudaGetSymbolAddress((void**)&pqhi, g_qhi);
    cudaGetSymbolAddress((void**)&pqlo, g_qlo);
    cudaGetSymbolAddress((void**)&pkhi, g_khi);
    cudaGetSymbolAddress((void**)&pklo, g_klo);
    cudaGetSymbolAddress((void**)&pvthi, g_vthi);
    cudaGetSymbolAddress((void**)&pvtlo, g_vtlo);

    cudaFuncSetAttribute(gemm_hmma,  cudaFuncAttributeMaxDynamicSharedMemorySize, GEMM_SMEM);
    cudaFuncSetAttribute(gemm_qkv3,  cudaFuncAttributeMaxDynamicSharedMemorySize, GEMM_SMEM);
    cudaFuncSetAttribute(flash_hmma, cudaFuncAttributeMaxDynamicSharedMemorySize, FB_SMEM);

    // #1 q+k split ([hi|lo])
    split_qk_kernel<<<12288, 256>>>(q, k, qs, ks);
    // #2 Wq+Wk split
    split_wqk_kernel<<<1536, 256>>>(Wq, Wk, wqs, wks);
    // #3 v + Wv + Wo split
    split_vwo_kernel<<<3072, 256>>>(v, Wv, Wo, vs, wvs, wos);
    // #4 merged q+k+v projections (PROFILED launch), segment-remapped loader
    gemm_qkv3<<<dim3(4, 32, 3), 256, GEMM_SMEM>>>(qs, wqs, qh, ks, wks, kh,
                                                  vs, wvs, vh,
                                                  D_EMB, D_AUG, D_AUG);
    // #5 rope table
    rope_table_kernel<<<512, 256>>>(rtab);
    // #6 rope + plane split
    rope_split_kernel<<<4096, 256>>>(qh, kh, rtab, pqhi, pqlo, pkhi, pklo);
    // #7 V transpose + split
    vt_split_kernel<<<dim3(64, 4, 8), dim3(32, 32)>>>(vh, pvthi, pvtlo);
    // #8 flash attention (double-buffered KV)
    flash_hmma<<<dim3(16, 8), 256, FB_SMEM>>>(pqhi, pqlo, pkhi, pklo, pvthi, pvtlo, ats);
    // #9 output projection (segment-remapped)
    gemm_hmma<<<dim3(12, 32), 256, GEMM_SMEM>>>(ats, wos, out, D_AUG, D_EMB);
}

// round 17
// speedup vs baseline: 1.0383x; 1.0383x over previous
#include <cuda_runtime.h>
#include <cuda_bf16.h>
#include <math.h>
#include <stdint.h>

#define BS_TOT 4096
#define S_LEN  2048
#define D_EMB  1536
#define D_AUG  512

// ---------------- device scratch ----------------
__device__ float g_qh[BS_TOT * D_AUG];
__device__ float g_kh[BS_TOT * D_AUG];
__device__ float g_vh[BS_TOT * D_AUG];
__device__ float g_rope[2 * S_LEN * 64];   // cos | sin

// 3-term split operands: A-side rows [hi|hi|lo], B-side rows [hi|lo|hi]
__device__ __align__(128) __nv_bfloat16 g_q_s   [BS_TOT * 3 * D_EMB];
__device__ __align__(128) __nv_bfloat16 g_k_s   [BS_TOT * 3 * D_EMB];
__device__ __align__(128) __nv_bfloat16 g_v_s   [BS_TOT * 3 * D_AUG];
__device__ __align__(128) __nv_bfloat16 g_attn_s[BS_TOT * 3 * D_AUG];
__device__ __align__(128) __nv_bfloat16 g_Wq_s  [D_AUG * 3 * D_EMB];
__device__ __align__(128) __nv_bfloat16 g_Wk_s  [D_AUG * 3 * D_EMB];
__device__ __align__(128) __nv_bfloat16 g_Wv_s  [D_AUG * 3 * D_AUG];
__device__ __align__(128) __nv_bfloat16 g_Wo_s  [D_EMB * 3 * D_AUG];

__device__ __align__(128) __nv_bfloat16 g_qhi[8 * S_LEN * 128];
__device__ __align__(128) __nv_bfloat16 g_qlo[8 * S_LEN * 128];
__device__ __align__(128) __nv_bfloat16 g_khi[8 * S_LEN * 128];
__device__ __align__(128) __nv_bfloat16 g_klo[8 * S_LEN * 128];
__device__ __align__(128) __nv_bfloat16 g_vthi[8 * 128 * S_LEN];
__device__ __align__(128) __nv_bfloat16 g_vtlo[8 * 128 * S_LEN];

extern __shared__ __align__(128) char dynsmem[];

#define PAIR_BAR(id) asm volatile("bar.sync %0, 64;" :: "r"(id) : "memory")

// ---------------------------------------------------------------------------
__device__ __forceinline__ uint32_t smem_u32(const void* p) {
    uint32_t a;
    asm("{ .reg .u64 t; cvta.to.shared.u64 t, %1; cvt.u32.u64 %0, t; }" : "=r"(a) : "l"(p));
    return a;
}
__device__ __forceinline__ void cp16(uint32_t saddr, const void* gaddr) {
    asm volatile("cp.async.cg.shared.global [%0], [%1], 16;" :: "r"(saddr), "l"(gaddr) : "memory");
}
__device__ __forceinline__ void cp_commit() {
    asm volatile("cp.async.commit_group;" ::: "memory");
}
template <int N>
__device__ __forceinline__ void cp_wait() {
    asm volatile("cp.async.wait_group %0;" :: "n"(N) : "memory");
}
__device__ __forceinline__ void ldmx4(uint32_t* r, uint32_t addr) {
    asm volatile("ldmatrix.sync.aligned.m8n8.x4.shared.b16 {%0,%1,%2,%3}, [%4];"
                 : "=r"(r[0]), "=r"(r[1]), "=r"(r[2]), "=r"(r[3]) : "r"(addr));
}
__device__ __forceinline__ void mma_bf16(float* c, const uint32_t* a, uint32_t b0, uint32_t b1) {
    asm volatile(
        "mma.sync.aligned.m16n8k16.row.col.f32.bf16.bf16.f32 "
        "{%0,%1,%2,%3}, {%4,%5,%6,%7}, {%8,%9}, {%0,%1,%2,%3};"
        : "+f"(c[0]), "+f"(c[1]), "+f"(c[2]), "+f"(c[3])
        : "r"(a[0]), "r"(a[1]), "r"(a[2]), "r"(a[3]), "r"(b0), "r"(b1));
}
__device__ __forceinline__ float ex2(float x) {
    float y; asm("ex2.approx.f32 %0, %1;" : "=f"(y) : "f"(x)); return y;
}

// ---------------------------------------------------------------------------
// split: dst rows length 3K; bmode=0: [hi|hi|lo], bmode=1: [hi|lo|hi]
// ---------------------------------------------------------------------------
__device__ __forceinline__ void split3_row(const float* srow, __nv_bfloat16* drow,
                                           int K, int c4, int bmode)
{
    float4 x = *(const float4*)(srow + c4);
    float xs[4] = {x.x, x.y, x.z, x.w};
    __nv_bfloat162 h0, h1, l0, l1;
    __nv_bfloat16 h[4], l[4];
#pragma unroll
    for (int j = 0; j < 4; j++) {
        h[j] = __float2bfloat16(xs[j]);
        l[j] = __float2bfloat16(xs[j] - __bfloat162float(h[j]));
    }
    h0.x = h[0]; h0.y = h[1]; h1.x = h[2]; h1.y = h[3];
    l0.x = l[0]; l0.y = l[1]; l1.x = l[2]; l1.y = l[3];
    __nv_bfloat16* d = drow + c4;
    *(__nv_bfloat162*)(d)     = h0;  *(__nv_bfloat162*)(d + 2)     = h1;
    if (bmode == 0) {
        *(__nv_bfloat162*)(d + K)     = h0;  *(__nv_bfloat162*)(d + K + 2)     = h1;
        *(__nv_bfloat162*)(d + 2 * K) = l0;  *(__nv_bfloat162*)(d + 2 * K + 2) = l1;
    } else {
        *(__nv_bfloat162*)(d + K)     = l0;  *(__nv_bfloat162*)(d + K + 2)     = l1;
        *(__nv_bfloat162*)(d + 2 * K) = h0;  *(__nv_bfloat162*)(d + 2 * K + 2) = h1;
    }
}

__global__ void split_qk_kernel(const float* __restrict__ q, const float* __restrict__ k,
                                __nv_bfloat16* __restrict__ qs, __nv_bfloat16* __restrict__ ks)
{
    int i = blockIdx.x * blockDim.x + threadIdx.x;       // 8192*384
    int rt = i / 384, c4 = (i - rt * 384) << 2;
    const float* src = (rt < 4096) ? q : k;
    __nv_bfloat16* dst = (rt < 4096) ? qs : ks;
    int r = rt & 4095;
    split3_row(src + (size_t)r * D_EMB, dst + (size_t)r * 3 * D_EMB, D_EMB, c4, 0);
}

__global__ void split_wqk_kernel(const float* __restrict__ Wq, const float* __restrict__ Wk,
                                 __nv_bfloat16* __restrict__ wqs, __nv_bfloat16* __restrict__ wks)
{
    int i = blockIdx.x * blockDim.x + threadIdx.x;       // 1024*384
    int rt = i / 384, c4 = (i - rt * 384) << 2;
    const float* src = (rt < 512) ? Wq : Wk;
    __nv_bfloat16* dst = (rt < 512) ? wqs : wks;
    int r = rt & 511;
    split3_row(src + (size_t)r * D_EMB, dst + (size_t)r * 3 * D_EMB, D_EMB, c4, 1);
}

// v (4096 rows, stride D_EMB, offset D_AUG), Wv (512, stride D_AUG),
// Wo (1536 rows, stride D_EMB — W_o is 1536x1536, cols [0,512)).
__global__ void split_vwo_kernel(const float* __restrict__ v, const float* __restrict__ Wv,
                                 const float* __restrict__ Wo,
                                 __nv_bfloat16* __restrict__ vs, __nv_bfloat16* __restrict__ wvs,
                                 __nv_bfloat16* __restrict__ wos)
{
    int i = blockIdx.x * blockDim.x + threadIdx.x;       // 6144*128
    int rt = i >> 7, c4 = (i & 127) << 2;
    if (rt < 4096) {
        split3_row(v + (size_t)rt * D_EMB + D_AUG, vs + (size_t)rt * 3 * D_AUG, D_AUG, c4, 0);
    } else if (rt < 4608) {
        int r = rt - 4096;
        split3_row(Wv + (size_t)r * D_AUG, wvs + (size_t)r * 3 * D_AUG, D_AUG, c4, 1);
    } else {
        int r = rt - 4608;
        split3_row(Wo + (size_t)r * D_EMB, wos + (size_t)r * 3 * D_AUG, D_AUG, c4, 1);
    }
}

// ---------------------------------------------------------------------------
// HMMA GEMM core (R13/R15-proven): C[M,N] = A[M,K3] @ B[N,K3]^T, BK=32
// ---------------------------------------------------------------------------
#define BM 128
#define BN 128
#define BK 32
#define LDSM 40
#define STAGES 3
#define TSTG (BM * LDSM)
#define GEMM_SMEM (2 * STAGES * TSTG * 2)

__device__ __forceinline__ void gemm_body(const __nv_bfloat16* __restrict__ A,
                                          const __nv_bfloat16* __restrict__ B,
                                          float* __restrict__ C, int K3, int ldc,
                                          int m0, int n0)
{
    __nv_bfloat16* As = (__nv_bfloat16*)dynsmem;
    __nv_bfloat16* Bs = As + STAGES * TSTG;

    const int tid  = threadIdx.x;
    const int wid  = tid >> 5, lane = tid & 31;
    const int wm   = (wid >> 2) * 64;
    const int wn   = (wid & 3) * 32;

    const int lrow0 = tid >> 2,         lq0 = tid & 3;
    const int lrow1 = (tid + 256) >> 2, lq1 = (tid + 256) & 3;

    const __nv_bfloat16* Ag0 = A + (size_t)(m0 + lrow0) * K3 + lq0 * 8;
    const __nv_bfloat16* Ag1 = A + (size_t)(m0 + lrow1) * K3 + lq1 * 8;
    const __nv_bfloat16* Bg0 = B + (size_t)(n0 + lrow0) * K3 + lq0 * 8;
    const __nv_bfloat16* Bg1 = B + (size_t)(n0 + lrow1) * K3 + lq1 * 8;
    const uint32_t sA0 = smem_u32(As) + (lrow0 * LDSM + lq0 * 8) * 2;
    const uint32_t sA1 = smem_u32(As) + (lrow1 * LDSM + lq1 * 8) * 2;
    const uint32_t sB0 = smem_u32(Bs) + (lrow0 * LDSM + lq0 * 8) * 2;
    const uint32_t sB1 = smem_u32(Bs) + (lrow1 * LDSM + lq1 * 8) * 2;

    const int KT = K3 / BK;

    float acc[4][4][4];
#pragma unroll
    for (int i = 0; i < 4; i++)
#pragma unroll
        for (int j = 0; j < 4; j++)
#pragma unroll
            for (int t = 0; t < 4; t++) acc[i][j][t] = 0.f;

    const uint32_t als = smem_u32(As) + ((wm + (lane & 15)) * LDSM + (lane >> 4) * 8) * 2;
    const uint32_t bls = smem_u32(Bs) + ((wn + (lane & 15)) * LDSM + (lane >> 4) * 8) * 2;

#pragma unroll
    for (int s = 0; s < STAGES - 1; s++) {
        int k0 = s * BK;
        cp16(sA0 + s * TSTG * 2, Ag0 + k0);
        cp16(sA1 + s * TSTG * 2, Ag1 + k0);
        cp16(sB0 + s * TSTG * 2, Bg0 + k0);
        cp16(sB1 + s * TSTG * 2, Bg1 + k0);
        cp_commit();
    }

    for (int it = 0; it < KT; it++) {
        cp_wait<STAGES - 2>();
        __syncthreads();
        const int sc = it % STAGES;
        const uint32_t abase = als + sc * TSTG * 2;
        const uint32_t bbase = bls + sc * TSTG * 2;
#pragma unroll
        for (int ks = 0; ks < 2; ks++) {
            uint32_t af[4][4], bf[2][4];
#pragma unroll
            for (int mt = 0; mt < 4; mt++)
                ldmx4(af[mt], abase + (mt * 16 * LDSM + ks * 16) * 2);
#pragma unroll
            for (int nt2 = 0; nt2 < 2; nt2++)
                ldmx4(bf[nt2], bbase + (nt2 * 16 * LDSM + ks * 16) * 2);
#pragma unroll
            for (int mt = 0; mt < 4; mt++)
#pragma unroll
                for (int nt = 0; nt < 4; nt++)
                    mma_bf16(acc[mt][nt], af[mt],
                             bf[nt >> 1][nt & 1], bf[nt >> 1][(nt & 1) + 2]);
        }
        const int nxt = it + STAGES - 1;
        if (nxt < KT) {
            const int sn = nxt % STAGES;
            const int k0 = nxt * BK;
            cp16(sA0 + sn * TSTG * 2, Ag0 + k0);
            cp16(sA1 + sn * TSTG * 2, Ag1 + k0);
            cp16(sB0 + sn * TSTG * 2, Bg0 + k0);
            cp16(sB1 + sn * TSTG * 2, Bg1 + k0);
        }
        cp_commit();
    }

    const int rbase = m0 + wm + (lane >> 2);
    const int cbase = n0 + wn + (lane & 3) * 2;
#pragma unroll
    for (int mt = 0; mt < 4; mt++) {
#pragma unroll
        for (int nt = 0; nt < 4; nt++) {
            float* p0 = C + (size_t)(rbase + mt * 16) * ldc + cbase + nt * 8;
            float* p1 = p0 + 8 * ldc;
            *(float2*)p0 = make_float2(acc[mt][nt][0], acc[mt][nt][1]);
            *(float2*)p1 = make_float2(acc[mt][nt][2], acc[mt][nt][3]);
        }
    }
}

__global__ void __launch_bounds__(256, 2)
gemm_hmma(const __nv_bfloat16* __restrict__ A, const __nv_bfloat16* __restrict__ B,
          float* __restrict__ C, int K3, int ldc)
{
    gemm_body(A, B, C, K3, ldc, blockIdx.y * BM, blockIdx.x * BN);
}

__global__ void __launch_bounds__(256, 2)
gemm_qkv3(const __nv_bfloat16* __restrict__ A0, const __nv_bfloat16* __restrict__ B0, float* __restrict__ C0,
          const __nv_bfloat16* __restrict__ A1, const __nv_bfloat16* __restrict__ B1, float* __restrict__ C1,
          const __nv_bfloat16* __restrict__ A2, const __nv_bfloat16* __restrict__ B2, float* __restrict__ C2,
          int K3qk, int K3v, int ldc)
{
    const int z = blockIdx.z;
    const __nv_bfloat16* A = (z == 0) ? A0 : (z == 1) ? A1 : A2;
    const __nv_bfloat16* B = (z == 0) ? B0 : (z == 1) ? B1 : B2;
    float* C = (z == 0) ? C0 : (z == 1) ? C1 : C2;
    const int K3 = (z == 2) ? K3v : K3qk;
    gemm_body(A, B, C, K3, ldc, blockIdx.y * BM, blockIdx.x * BN);
}

// ---------------------------------------------------------------------------
// RoPE table
// ---------------------------------------------------------------------------
__global__ void rope_table_kernel(float* __restrict__ tab)
{
    int idx = blockIdx.x * blockDim.x + threadIdx.x;   // 2048*64
    if (idx >= S_LEN * 64) return;
    int pair = idx & 63, s = idx >> 6;
    float freq = (float)exp(-(double)(2 * pair) * (1.0 / 128.0) * 9.210340371976184);
    float ang  = (float)s * freq;
    tab[idx]              = cosf(ang);
    tab[S_LEN * 64 + idx] = sinf(ang);
}

// ---------------------------------------------------------------------------
// RoPE + split-bf16 plane emission
// ---------------------------------------------------------------------------
__global__ void rope_split_kernel(const float* __restrict__ qh, const float* __restrict__ kh,
                                  const float* __restrict__ tab,
                                  __nv_bfloat16* __restrict__ qhi, __nv_bfloat16* __restrict__ qlo,
                                  __nv_bfloat16* __restrict__ khi, __nv_bfloat16* __restrict__ klo)
{
    int idx  = blockIdx.x * blockDim.x + threadIdx.x;  // 8*2048*64
    int pair = idx & 63;
    int s    = (idx >> 6) & (S_LEN - 1);
    int bh   = idx >> 17;
    int b = bh >> 2, h = bh & 3;

    float c  = tab[s * 64 + pair];
    float sn = tab[S_LEN * 64 + s * 64 + pair];

    size_t src = (size_t)(b * S_LEN + s) * D_AUG + h * 128 + 2 * pair;
    size_t dst = (size_t)bh * S_LEN * 128 + (size_t)s * 128 + 2 * pair;
    const float qscale = 0.08838834764831845f;

    float q1 = qh[src], q2 = qh[src + 1];
    float qa = (q1 * c - q2 * sn) * qscale;
    float qb = (q1 * sn + q2 * c) * qscale;
    __nv_bfloat16 ha = __float2bfloat16(qa), hb = __float2bfloat16(qb);
    __nv_bfloat162 hv; hv.x = ha; hv.y = hb;
    __nv_bfloat162 lv;
    lv.x = __float2bfloat16(qa - __bfloat162float(ha));
    lv.y = __float2bfloat16(qb - __bfloat162float(hb));
    *(__nv_bfloat162*)(qhi + dst) = hv;
    *(__nv_bfloat162*)(qlo + dst) = lv;

    float k1 = kh[src], k2 = kh[src + 1];
    float ka = k1 * c - k2 * sn;
    float kb = k1 * sn + k2 * c;
    ha = __float2bfloat16(ka); hb = __float2bfloat16(kb);
    hv.x = ha; hv.y = hb;
    lv.x = __float2bfloat16(ka - __bfloat162float(ha));
    lv.y = __float2bfloat16(kb - __bfloat162float(hb));
    *(__nv_bfloat162*)(khi + dst) = hv;
    *(__nv_bfloat162*)(klo + dst) = lv;
}

// ---------------------------------------------------------------------------
// V transpose + split
// ---------------------------------------------------------------------------
__global__ void vt_split_kernel(const float* __restrict__ vh,
                                __nv_bfloat16* __restrict__ vthi, __nv_bfloat16* __restrict__ vtlo)
{
    __shared__ float tile[32][33];
    int bh = blockIdx.z, b = bh >> 2, h = bh & 3;
    int tx = threadIdx.x, ty = threadIdx.y;
    int s_in = blockIdx.x * 32 + ty;
    int d_in = blockIdx.y * 32 + tx;
    tile[ty][tx] = vh[(size_t)(b * S_LEN + s_in) * D_AUG + h * 128 + d_in];
    __syncthreads();
    int d_out = blockIdx.y * 32 + ty;
    int s_out = blockIdx.x * 32 + tx;
    float v = tile[tx][ty];
    __nv_bfloat16 hi = __float2bfloat16(v);
    size_t dst = (size_t)bh * 128 * S_LEN + (size_t)d_out * S_LEN + s_out;
    vthi[dst] = hi;
    vtlo[dst] = __float2bfloat16(v - __bfloat162float(hi));
}

// ---------------------------------------------------------------------------
// HMMA flash attention, double-buffered KV; reduction barriers are pairwise
// (bar.sync 1+mw, 64) since only the nw=0/1 warps of a row-group exchange.
// ---------------------------------------------------------------------------
#define FB_QHI  0
#define FB_QLO  17408
#define FB_KV0  34816
#define FB_KV1  106496
#define KV_KHI  0
#define KV_KLO  17408
#define KV_VHI  34816
#define KV_VLO  53248
#define FB_PHI  178176
#define FB_PLO  187392
#define FB_RED  196608
#define FB_SMEM 197632
#define L2E 1.4426950408889634f

__global__ void __launch_bounds__(256, 1)
flash_hmma(const __nv_bfloat16* __restrict__ qhi, const __nv_bfloat16* __restrict__ qlo,
           const __nv_bfloat16* __restrict__ khi, const __nv_bfloat16* __restrict__ klo,
           const __nv_bfloat16* __restrict__ vthi, const __nv_bfloat16* __restrict__ vtlo,
           __nv_bfloat16* __restrict__ attn_s)
{
    char* fsm = dynsmem;
    const uint32_t sb = smem_u32(fsm);
    float* red = (float*)(fsm + FB_RED);

    const int tid  = threadIdx.x;
    const int lane = tid & 31;
    const int wid  = tid >> 5;
    const int mw   = wid >> 1;
    const int nw   = wid & 1;
    const int bh   = blockIdx.y;
    const int b    = bh >> 2, hh = bh & 3;
    const int pbar = 1 + mw;

    const size_t qkplane = (size_t)bh * S_LEN * 128;
    const size_t vplane  = (size_t)bh * 128 * S_LEN;

    const uint32_t aoffQ = (mw * 16 + (lane & 15)) * 272 + (lane >> 4) * 16;
    const uint32_t boffK = (nw * 32 + (lane & 15)) * 272 + (lane >> 4) * 16;
    const uint32_t aoffP = (mw * 16 + (lane & 15)) * 144 + (lane >> 4) * 16;
    const uint32_t boffV = (nw * 64 + (lane & 15)) * 144 + (lane >> 4) * 16;

    const int r0 = lane >> 2;
    const int c2 = (lane & 3) * 2;
    const int rloc0 = mw * 16 + r0;
    const int rloc1 = rloc0 + 8;

    const int kr[4]  = {tid >> 4, (tid + 256) >> 4, (tid + 512) >> 4, (tid + 768) >> 4};
    const int kq[4]  = {tid & 15, (tid + 256) & 15, (tid + 512) & 15, (tid + 768) & 15};
    const int vr[4]  = {tid >> 3, (tid + 256) >> 3, (tid + 512) >> 3, (tid + 768) >> 3};
    const int vq[4]  = {tid & 7,  (tid + 256) & 7,  (tid + 512) & 7,  (tid + 768) & 7};

    for (int qq = 0; qq < 2; qq++) {
        const int qb = qq ? 31 - (int)blockIdx.x : (int)blockIdx.x;

        __syncthreads();
        {
            const __nv_bfloat16* srcs[2] = {qhi + qkplane + (size_t)qb * 64 * 128,
                                            qlo + qkplane + (size_t)qb * 64 * 128};
#pragma unroll
            for (int p = 0; p < 2; p++)
#pragma unroll
                for (int i = 0; i < 4; i++)
                    cp16(sb + FB_QHI + p * 17408 + kr[i] * 272 + kq[i] * 16,
                         srcs[p] + (size_t)kr[i] * 128 + kq[i] * 8);
            cp_commit();
        }
        {
            const __nv_bfloat16* ks[2] = {khi + qkplane, klo + qkplane};
            const __nv_bfloat16* vs[2] = {vthi + vplane, vtlo + vplane};
#pragma unroll
            for (int p = 0; p < 2; p++)
#pragma unroll
                for (int i = 0; i < 4; i++)
                    cp16(sb + FB_KV0 + KV_KHI + p * 17408 + kr[i] * 272 + kq[i] * 16,
                         ks[p] + (size_t)kr[i] * 128 + kq[i] * 8);
#pragma unroll
            for (int p = 0; p < 2; p++)
#pragma unroll
                for (int i = 0; i < 4; i++)
                    cp16(sb + FB_KV0 + KV_VHI + p * 18432 + vr[i] * 144 + vq[i] * 16,
                         vs[p] + (size_t)vr[i] * S_LEN + vq[i] * 8);
            cp_commit();
        }

        float m0 = -1e30f, m1 = -1e30f, l0 = 0.f, l1 = 0.f;
        float o[8][4];
#pragma unroll
        for (int f = 0; f < 8; f++)
#pragma unroll
            for (int e = 0; e < 4; e++) o[f][e] = 0.f;

        for (int jb = 0; jb <= qb; jb++) {
            __syncthreads();
            if (jb < qb) {
                const int nj = jb + 1;
                const uint32_t nb = sb + ((nj & 1) ? FB_KV1 : FB_KV0);
                const __nv_bfloat16* ks[2] = {khi + qkplane + (size_t)nj * 64 * 128,
                                              klo + qkplane + (size_t)nj * 64 * 128};
                const __nv_bfloat16* vs[2] = {vthi + vplane + nj * 64,
                                              vtlo + vplane + nj * 64};
#pragma unroll
                for (int p = 0; p < 2; p++)
#pragma unroll
                    for (int i = 0; i < 4; i++)
                        cp16(nb + KV_KHI + p * 17408 + kr[i] * 272 + kq[i] * 16,
                             ks[p] + (size_t)kr[i] * 128 + kq[i] * 8);
#pragma unroll
                for (int p = 0; p < 2; p++)
#pragma unroll
                    for (int i = 0; i < 4; i++)
                        cp16(nb + KV_VHI + p * 18432 + vr[i] * 144 + vq[i] * 16,
                             vs[p] + (size_t)vr[i] * S_LEN + vq[i] * 8);
            }
            cp_commit();
            cp_wait<1>();
            __syncthreads();

            const uint32_t kvb = sb + ((jb & 1) ? FB_KV1 : FB_KV0);

            float sacc[4][4];
#pragma unroll
            for (int f = 0; f < 4; f++)
#pragma unroll
                for (int e = 0; e < 4; e++) sacc[f][e] = 0.f;

            const uint32_t aB[3] = {sb + FB_QHI, sb + FB_QHI, sb + FB_QLO};
            const uint32_t bB[3] = {kvb + KV_KHI, kvb + KV_KLO, kvb + KV_KHI};
#pragma unroll
            for (int ps = 0; ps < 3; ps++) {
                const uint32_t ab = aB[ps] + aoffQ;
                const uint32_t bb0 = bB[ps] + boffK;
                const uint32_t bb1 = bb0 + 16 * 272;
#pragma unroll
                for (int ks = 0; ks < 8; ks++) {
                    uint32_t a[4], q0[4], q1[4];
                    ldmx4(a,  ab  + ks * 32);
                    ldmx4(q0, bb0 + ks * 32);
                    ldmx4(q1, bb1 + ks * 32);
                    mma_bf16(sacc[0], a, q0[0], q0[2]);
                    mma_bf16(sacc[1], a, q0[1], q0[3]);
                    mma_bf16(sacc[2], a, q1[0], q1[2]);
                    mma_bf16(sacc[3], a, q1[1], q1[3]);
                }
            }

            if (jb == qb) {
#pragma unroll
                for (int f = 0; f < 4; f++) {
                    int colb = nw * 32 + (f >> 1) * 16 + (f & 1) * 8 + c2;
#pragma unroll
                    for (int e = 0; e < 4; e++) {
                        int row = mw * 16 + r0 + ((e >> 1) << 3);
                        int col = colb + (e & 1);
                        if (col > row) sacc[f][e] = -1e30f;
                    }
                }
            }

            float pm0 = -1e30f, pm1 = -1e30f;
#pragma unroll
            for (int f = 0; f < 4; f++) {
                pm0 = fmaxf(pm0, fmaxf(sacc[f][0], sacc[f][1]));
                pm1 = fmaxf(pm1, fmaxf(sacc[f][2], sacc[f][3]));
            }
            pm0 = fmaxf(pm0, __shfl_xor_sync(0xffffffffu, pm0, 1));
            pm0 = fmaxf(pm0, __shfl_xor_sync(0xffffffffu, pm0, 2));
            pm1 = fmaxf(pm1, __shfl_xor_sync(0xffffffffu, pm1, 1));
            pm1 = fmaxf(pm1, __shfl_xor_sync(0xffffffffu, pm1, 2));
            if ((lane & 3) == 0) {
                red[nw * 64 + rloc0] = pm0;
                red[nw * 64 + rloc1] = pm1;
            }
            PAIR_BAR(pbar);
            float rm0 = fmaxf(red[rloc0], red[64 + rloc0]);
            float rm1 = fmaxf(red[rloc1], red[64 + rloc1]);
            float mn0 = fmaxf(m0, rm0), mn1 = fmaxf(m1, rm1);
            float scl0 = ex2((m0 - mn0) * L2E);
            float scl1 = ex2((m1 - mn1) * L2E);

            float ts0 = 0.f, ts1 = 0.f;
#pragma unroll
            for (int f = 0; f < 4; f++) {
                int col = nw * 32 + (f >> 1) * 16 + (f & 1) * 8 + c2;
                float p00 = ex2((sacc[f][0] - mn0) * L2E);
                float p01 = ex2((sacc[f][1] - mn0) * L2E);
                float p10 = ex2((sacc[f][2] - mn1) * L2E);
                float p11 = ex2((sacc[f][3] - mn1) * L2E);
                ts0 += p00 + p01;
                ts1 += p10 + p11;
                __nv_bfloat16 h00 = __float2bfloat16(p00), h01 = __float2bfloat16(p01);
                __nv_bfloat16 h10 = __float2bfloat16(p10), h11 = __float2bfloat16(p11);
                __nv_bfloat162 hv, lv;
                hv.x = h00; hv.y = h01;
                lv.x = __float2bfloat16(p00 - __bfloat162float(h00));
                lv.y = __float2bfloat16(p01 - __bfloat162float(h01));
                *(__nv_bfloat162*)(fsm + FB_PHI + rloc0 * 144 + col * 2) = hv;
                *(__nv_bfloat162*)(fsm + FB_PLO + rloc0 * 144 + col * 2) = lv;
                hv.x = h10; hv.y = h11;
                lv.x = __float2bfloat16(p10 - __bfloat162float(h10));
                lv.y = __float2bfloat16(p11 - __bfloat162float(h11));
                *(__nv_bfloat162*)(fsm + FB_PHI + rloc1 * 144 + col * 2) = hv;
                *(__nv_bfloat162*)(fsm + FB_PLO + rloc1 * 144 + col * 2) = lv;
            }
            ts0 += __shfl_xor_sync(0xffffffffu, ts0, 1);
            ts0 += __shfl_xor_sync(0xffffffffu, ts0, 2);
            ts1 += __shfl_xor_sync(0xffffffffu, ts1, 1);
            ts1 += __shfl_xor_sync(0xffffffffu, ts1, 2);
            if ((lane & 3) == 0) {
                red[128 + nw * 64 + rloc0] = ts0;
                red[128 + nw * 64 + rloc1] = ts1;
            }
            PAIR_BAR(pbar);
            l0 = l0 * scl0 + red[128 + rloc0] + red[128 + 64 + rloc0];
            l1 = l1 * scl1 + red[128 + rloc1] + red[128 + 64 + rloc1];
            m0 = mn0; m1 = mn1;
#pragma unroll
            for (int f = 0; f < 8; f++) {
                o[f][0] *= scl0; o[f][1] *= scl0;
                o[f][2] *= scl1; o[f][3] *= scl1;
            }

            const uint32_t aP[3] = {sb + FB_PHI, sb + FB_PHI, sb + FB_PLO};
            const uint32_t bV[3] = {kvb + KV_VHI, kvb + KV_VLO, kvb + KV_VHI};
#pragma unroll
            for (int ps = 0; ps < 3; ps++) {
                const uint32_t ab = aP[ps] + aoffP;
                const uint32_t bb = bV[ps] + boffV;
#pragma unroll
                for (int ks = 0; ks < 4; ks++) {
                    uint32_t a[4];
                    ldmx4(a, ab + ks * 32);
#pragma unroll
                    for (int g2 = 0; g2 < 4; g2++) {
                        uint32_t qv[4];
                        ldmx4(qv, bb + g2 * (16 * 144) + ks * 32);
                        mma_bf16(o[g2 * 2 + 0], a, qv[0], qv[2]);
                        mma_bf16(o[g2 * 2 + 1], a, qv[1], qv[3]);
                    }
                }
            }
        }

        float inv0 = 1.0f / l0, inv1 = 1.0f / l1;
        size_t rg0 = (size_t)(b * S_LEN + qb * 64 + rloc0) * (3 * D_AUG);
        size_t rg1 = (size_t)(b * S_LEN + qb * 64 + rloc1) * (3 * D_AUG);
#pragma unroll
        for (int f = 0; f < 8; f++) {
            int col = hh * 128 + nw * 64 + (f >> 1) * 16 + (f & 1) * 8 + c2;
            float v0 = o[f][0] * inv0, v1 = o[f][1] * inv0;
            __nv_bfloat16 h0 = __float2bfloat16(v0), h1 = __float2bfloat16(v1);
            __nv_bfloat162 hv, lv;
            hv.x = h0; hv.y = h1;
            lv.x = __float2bfloat16(v0 - __bfloat162float(h0));
            lv.y = __float2bfloat16(v1 - __bfloat162float(h1));
            *(__nv_bfloat162*)(attn_s + rg0 + col)             = hv;
            *(__nv_bfloat162*)(attn_s + rg0 + col + D_AUG)     = hv;
            *(__nv_bfloat162*)(attn_s + rg0 + col + 2 * D_AUG) = lv;
            v0 = o[f][2] * inv1; v1 = o[f][3] * inv1;
            h0 = __float2bfloat16(v0); h1 = __float2bfloat16(v1);
            hv.x = h0; hv.y = h1;
            lv.x = __float2bfloat16(v0 - __bfloat162float(h0));
            lv.y = __float2bfloat16(v1 - __bfloat162float(h1));
            *(__nv_bfloat162*)(attn_s + rg1 + col)             = hv;
            *(__nv_bfloat162*)(attn_s + rg1 + col + D_AUG)     = hv;
            *(__nv_bfloat162*)(attn_s + rg1 + col + 2 * D_AUG) = lv;
        }
    }
}

// ---------------------------------------------------------------------------
extern "C" void kernel_launch(void* const* d_in, const int* in_sizes, int n_in,
                              void* d_out, int out_size)
{
    const float* q  = (const float*)d_in[0];
    const float* k  = (const float*)d_in[1];
    const float* v  = (const float*)d_in[2];
    const float* Wq = (const float*)d_in[3];
    const float* Wk = (const float*)d_in[4];
    const float* Wv = (const float*)d_in[5];
    const float* Wo = (const float*)d_in[6];
    float* out = (float*)d_out;

    float *qh, *kh, *vh, *rtab;
    cudaGetSymbolAddress((void**)&qh,   g_qh);
    cudaGetSymbolAddress((void**)&kh,   g_kh);
    cudaGetSymbolAddress((void**)&vh,   g_vh);
    cudaGetSymbolAddress((void**)&rtab, g_rope);
    __nv_bfloat16 *qs, *ks, *vs, *ats, *wqs, *wks, *wvs, *wos;
    __nv_bfloat16 *pqhi, *pqlo, *pkhi, *pklo, *pvthi, *pvtlo;
    cudaGetSymbolAddress((void**)&qs,  g_q_s);
    cudaGetSymbolAddress((void**)&ks,  g_k_s);
    cudaGetSymbolAddress((void**)&vs,  g_v_s);
    cudaGetSymbolAddress((void**)&ats, g_attn_s);
    cudaGetSymbolAddress((void**)&wqs, g_Wq_s);
    cudaGetSymbolAddress((void**)&wks, g_Wk_s);
    cudaGetSymbolAddress((void**)&wvs, g_Wv_s);
    cudaGetSymbolAddress((void**)&wos, g_Wo_s);
    cudaGetSymbolAddress((void**)&pqhi, g_qhi);
    cudaGetSymbolAddress((void**)&pqlo, g_qlo);
    cudaGetSymbolAddress((void**)&pkhi, g_khi);
    cudaGetSymbolAddress((void**)&pklo, g_klo);
    cudaGetSymbolAddress((void**)&pvthi, g_vthi);
    cudaGetSymbolAddress((void**)&pvtlo, g_vtlo);

    cudaFuncSetAttribute(gemm_hmma,  cudaFuncAttributeMaxDynamicSharedMemorySize, GEMM_SMEM);
    cudaFuncSetAttribute(gemm_qkv3,  cudaFuncAttributeMaxDynamicSharedMemorySize, GEMM_SMEM);
    cudaFuncSetAttribute(flash_hmma, cudaFuncAttributeMaxDynamicSharedMemorySize, FB_SMEM);

    // #1 q+k split
    split_qk_kernel<<<12288, 256>>>(q, k, qs, ks);
    // #2 Wq+Wk split
    split_wqk_kernel<<<1536, 256>>>(Wq, Wk, wqs, wks);
    // #3 v + Wv + Wo split
    split_vwo_kernel<<<3072, 256>>>(v, Wv, Wo, vs, wvs, wos);
    // #4 merged q+k+v projections (PROFILED launch)
    gemm_qkv3<<<dim3(4, 32, 3), 256, GEMM_SMEM>>>(qs, wqs, qh, ks, wks, kh,
                                                  vs, wvs, vh,
                                                  3 * D_EMB, 3 * D_AUG, D_AUG);
    // #5 rope table
    rope_table_kernel<<<512, 256>>>(rtab);
    // #6 rope + plane split
    rope_split_kernel<<<4096, 256>>>(qh, kh, rtab, pqhi, pqlo, pkhi, pklo);
    // #7 V transpose + split
    vt_split_kernel<<<dim3(64, 4, 8), dim3(32, 32)>>>(vh, pvthi, pvtlo);
    // #8 flash attention (double-buffered KV, pair barriers)
    flash_hmma<<<dim3(16, 8), 256, FB_SMEM>>>(pqhi, pqlo, pkhi, pklo, pvthi, pvtlo, ats);
    // #9 output projection
    gemm_hmma<<<dim3(12, 32), 256, GEMM_SMEM>>>(ats, wos, out, 3 * D_AUG, D_EMB);
}